// round 5
// baseline (speedup 1.0000x reference)
#include <cuda_runtime.h>
#include <math.h>
#include <stdint.h>

// Problem constants (fixed-shape problem)
#define NA_N   40000
#define NB_N   40000
#define EPS_LN 1e-5f

#define WARPS_PER_BLK 8
#define EDGE_BLOCKS   148          // per edge type
#define EDGE_STRIDE   (EDGE_BLOCKS * WARPS_PER_BLK)
#define THREADS_BLK   (WARPS_PER_BLK * 32)

#define WSTR 68                     // padded weight row stride (floats): 272B = 17*16

// Scratch: per-type accumulators (pair-interleaved channel layout) and counts
__device__ float g_acc[2ull * NA_N * 256ull];
__device__ int   g_cnt[2 * NA_N];

// ---------------------------------------------------------------------------
// helpers
// ---------------------------------------------------------------------------
__device__ __forceinline__ float warp_sum(float v) {
#pragma unroll
    for (int o = 16; o; o >>= 1) v += __shfl_xor_sync(0xffffffffu, v, o);
    return v;
}
__device__ __forceinline__ float warp_max(float v) {
#pragma unroll
    for (int o = 16; o; o >>= 1) v = fmaxf(v, __shfl_xor_sync(0xffffffffu, v, o));
    return v;
}

// packed fp32x2 FMA: acc += x * w elementwise on the 2-lane pair
__device__ __forceinline__ void ffma2(uint64_t& acc, uint64_t x, uint64_t w) {
    asm("fma.rn.f32x2 %0, %1, %2, %0;" : "+l"(acc) : "l"(x), "l"(w));
}
__device__ __forceinline__ float u64_lo(uint64_t a) { return __uint_as_float((unsigned)(a & 0xffffffffu)); }
__device__ __forceinline__ float u64_hi(uint64_t a) { return __uint_as_float((unsigned)(a >> 32)); }
__device__ __forceinline__ float u64_sum(uint64_t a) { return u64_lo(a) + u64_hi(a); }

// Packed GEMM core: in [S][instride] canonical channels; W rows [f][WSTR] row-major.
// Lane computes output features f0=lane, f1=lane+32 for each of S tokens.
// Accumulator halves hold (even,odd) reduction-channel partials -> add at end.
template <int S>
__device__ __forceinline__ void mmp1_core(const float* __restrict__ in, int instride,
                                          const float* __restrict__ W, int lane,
                                          uint64_t (&a0)[S], uint64_t (&a1)[S]) {
#pragma unroll
    for (int s = 0; s < S; s++) { a0[s] = 0ull; a1[s] = 0ull; }
    const float* w0p = W + lane * WSTR;
    const float* w1p = W + (lane + 32) * WSTR;
#pragma unroll
    for (int c4 = 0; c4 < 16; c4++) {
        ulonglong2 w0 = *reinterpret_cast<const ulonglong2*>(w0p + c4 * 4);
        ulonglong2 w1 = *reinterpret_cast<const ulonglong2*>(w1p + c4 * 4);
#pragma unroll
        for (int s = 0; s < S; s++) {
            ulonglong2 xv = *reinterpret_cast<const ulonglong2*>(in + s * instride + c4 * 4);
            ffma2(a0[s], xv.x, w0.x);
            ffma2(a0[s], xv.y, w0.y);
            ffma2(a1[s], xv.x, w1.x);
            ffma2(a1[s], xv.y, w1.y);
        }
    }
}

// Fused multi-matrix packed sweep: M weight groups at row offsets foff[m] in W.
template <int S, int M>
__device__ __forceinline__ void mmpM_core(const float* __restrict__ in, int instride,
                                          const float* __restrict__ W, const int* foff,
                                          int lane, uint64_t (*a0)[S], uint64_t (*a1)[S]) {
#pragma unroll
    for (int m = 0; m < M; m++)
#pragma unroll
        for (int s = 0; s < S; s++) { a0[m][s] = 0ull; a1[m][s] = 0ull; }
#pragma unroll
    for (int c4 = 0; c4 < 16; c4++) {
        ulonglong2 xv[S];
#pragma unroll
        for (int s = 0; s < S; s++)
            xv[s] = *reinterpret_cast<const ulonglong2*>(in + s * instride + c4 * 4);
#pragma unroll
        for (int m = 0; m < M; m++) {
            const float* w0p = W + (foff[m] + lane) * WSTR;
            const float* w1p = W + (foff[m] + lane + 32) * WSTR;
            ulonglong2 w0 = *reinterpret_cast<const ulonglong2*>(w0p + c4 * 4);
            ulonglong2 w1 = *reinterpret_cast<const ulonglong2*>(w1p + c4 * 4);
#pragma unroll
            for (int s = 0; s < S; s++) {
                ffma2(a0[m][s], xv[s].x, w0.x);
                ffma2(a0[m][s], xv[s].y, w0.y);
                ffma2(a1[m][s], xv[s].x, w1.x);
                ffma2(a1[m][s], xv[s].y, w1.y);
            }
        }
    }
}

// LayerNorm over 64 features distributed as (lane, lane+32).
__device__ __forceinline__ void ln_pair(float r0, float r1,
                                        const float* __restrict__ g, const float* __restrict__ b,
                                        int lane, float& y0, float& y1) {
    float m = warp_sum(r0 + r1) * (1.f / 64.f);
    float d0 = r0 - m, d1 = r1 - m;
    float v = warp_sum(d0 * d0 + d1 * d1) * (1.f / 64.f);
    float inv = rsqrtf(v + EPS_LN);
    y0 = d0 * inv * g[lane]      + b[lane];
    y1 = d1 * inv * g[lane + 32] + b[lane + 32];
}

// ---------------------------------------------------------------------------
// zero scratch
// ---------------------------------------------------------------------------
__global__ void zero_kernel() {
    size_t i = (size_t)blockIdx.x * blockDim.x + threadIdx.x;
    size_t stride = (size_t)gridDim.x * blockDim.x;
    float4* p = reinterpret_cast<float4*>(g_acc);
    size_t n4 = (2ull * NA_N * 256ull) / 4;
    for (size_t j = i; j < n4; j += stride) p[j] = make_float4(0.f, 0.f, 0.f, 0.f);
    for (size_t j = i; j < 2 * NA_N; j += stride) g_cnt[j] = 0;
}

// ---------------------------------------------------------------------------
// per-edge transformer. grid = 2*EDGE_BLOCKS: type = blockIdx&1.
// One warp = one edge; only tokens 0..3 materialized after attention.
// Per-warp smem (1792 floats): xi[256] | xjff[256] | qox[256] | k[512] | v[512]
// ---------------------------------------------------------------------------
__global__ void __launch_bounds__(THREADS_BLK, 1) edge_kernel(
    const float* __restrict__ xA, const float* __restrict__ xB,
    const int* __restrict__ e0, int E0,
    const int* __restrict__ e1, int E1,
    const float* __restrict__ Wb,  const float* __restrict__ bb,
    const float* __restrict__ Wqkv,const float* __restrict__ bqkv,
    const float* __restrict__ Wo,  const float* __restrict__ bo,
    const float* __restrict__ g1,  const float* __restrict__ be1,
    const float* __restrict__ W1,  const float* __restrict__ bf1,
    const float* __restrict__ W2,  const float* __restrict__ bf2,
    const float* __restrict__ g2,  const float* __restrict__ be2) {
    extern __shared__ float smem[];
    float* sWb  = smem;               // [f][WSTR]    64*68
    float* sWq  = sWb + 64 * WSTR;    // [f][WSTR]    192*68 (q|k|v row groups)
    float* sWo  = sWq + 192 * WSTR;   // [f][WSTR]    64*68
    float* sW1  = sWo + 64 * WSTR;    // [f][WSTR]    64*68
    float* sW2  = sW1 + 64 * WSTR;    // [c_out][WSTR] 64*68 (reduction over FF)
    float* sbb  = sW2 + 64 * WSTR;    // 64
    float* sbq  = sbb + 64;           // 192
    float* sbo  = sbq + 192;          // 64
    float* sbf1 = sbo + 64;           // 64
    float* sbf2 = sbf1 + 64;          // 64
    float* sg1  = sbf2 + 64;
    float* sbe1 = sg1 + 64;
    float* sg2  = sbe1 + 64;
    float* sbe2 = sg2 + 64;
    float* bufs = sbe2 + 64;          // per-warp buffers: 1792 floats each

    const int type = blockIdx.x & 1;
    const int bidx = blockIdx.x >> 1;
    const int tid = threadIdx.x;

    // Stage weights: straight row-major copies with pad-to-WSTR rows
    {
        const float* p;
        p = Wb + type * 4096;
        for (int i = tid; i < 4096; i += THREADS_BLK)  { int f = i >> 6, c = i & 63; sWb[f * WSTR + c] = p[i]; }
        p = Wqkv + type * 12288;
        for (int i = tid; i < 12288; i += THREADS_BLK) { int f = i >> 6, c = i & 63; sWq[f * WSTR + c] = p[i]; }
        p = Wo + type * 4096;
        for (int i = tid; i < 4096; i += THREADS_BLK)  { int f = i >> 6, c = i & 63; sWo[f * WSTR + c] = p[i]; }
        p = W1 + type * 4096;
        for (int i = tid; i < 4096; i += THREADS_BLK)  { int f = i >> 6, c = i & 63; sW1[f * WSTR + c] = p[i]; }
        p = W2 + type * 4096;                          // [C][FF] row-major: reduction over FF
        for (int i = tid; i < 4096; i += THREADS_BLK)  { int c = i >> 6, f = i & 63; sW2[c * WSTR + f] = p[i]; }
        if (tid < 64)  sbb[tid]  = bb[type * 64 + tid];
        if (tid < 192) sbq[tid]  = bqkv[type * 192 + tid];
        if (tid < 64)  sbo[tid]  = bo[type * 64 + tid];
        if (tid < 64)  sbf1[tid] = bf1[type * 64 + tid];
        if (tid < 64)  sbf2[tid] = bf2[type * 64 + tid];
        if (tid < 64)  sg1[tid]  = g1[type * 64 + tid];
        if (tid < 64)  sbe1[tid] = be1[type * 64 + tid];
        if (tid < 64)  sg2[tid]  = g2[type * 64 + tid];
        if (tid < 64)  sbe2[tid] = be2[type * 64 + tid];
    }
    __syncthreads();

    const int warp = tid >> 5, lane = tid & 31;
    float* xi   = bufs + warp * 1792;
    float* xjff = xi + 256;
    float* qox  = xjff + 256;
    float* kbuf = qox + 256;     // xs staged here first (dead before k is written)
    float* vbuf = kbuf + 512;

    const float* xsrc = type ? xA : xB;
    const int*   ei   = type ? e1 : e0;
    const int    E    = type ? E1 : E0;
    float* accbase = g_acc + (size_t)type * NA_N * 256ull;
    int*   cntbase = g_cnt + type * NA_N;

    const int woff3[3] = {0, 64, 128};   // q, k, v row-group offsets in sWq
    const int woff2[2] = {64, 128};      // k, v

    for (int e = bidx * WARPS_PER_BLK + warp; e < E; e += EDGE_STRIDE) {
        const int src = __ldg(ei + e);
        const int dst = __ldg(ei + E + e);

        // Stage xi, xs (coalesced LDG.128 -> smem; later reads are LDS broadcast)
        {
            const float4* gxi = reinterpret_cast<const float4*>(xA + (size_t)dst * 256);
            const float4* gxs = reinterpret_cast<const float4*>(xsrc + (size_t)src * 256);
            float4 a = __ldg(gxi + lane);
            float4 b = __ldg(gxi + lane + 32);
            float4 c = __ldg(gxs + lane);
            float4 d = __ldg(gxs + lane + 32);
            reinterpret_cast<float4*>(xi)[lane]        = a;
            reinterpret_cast<float4*>(xi)[lane + 32]   = b;
            reinterpret_cast<float4*>(kbuf)[lane]      = c;
            reinterpret_cast<float4*>(kbuf)[lane + 32] = d;
        }
        __syncwarp();

        // b_proj: xs(kbuf) -> xjff
        {
            uint64_t a0[4], a1[4];
            mmp1_core<4>(kbuf, 64, sWb, lane, a0, a1);
            float b0 = sbb[lane], b1 = sbb[lane + 32];
#pragma unroll
            for (int s = 0; s < 4; s++) {
                xjff[s * 64 + lane]      = u64_sum(a0[s]) + b0;
                xjff[s * 64 + lane + 32] = u64_sum(a1[s]) + b1;
            }
        }
        __syncwarp();

        // fused q,k,v from xi (overwrites kbuf[0:256]: xs is dead)
        {
            uint64_t a0[3][4], a1[3][4];
            mmpM_core<4, 3>(xi, 64, sWq, woff3, lane, a0, a1);
            float bq0 = sbq[lane],       bq1 = sbq[lane + 32];
            float bk0 = sbq[64 + lane],  bk1 = sbq[64 + lane + 32];
            float bv0 = sbq[128 + lane], bv1 = sbq[128 + lane + 32];
#pragma unroll
            for (int s = 0; s < 4; s++) {
                qox[s * 64 + lane]       = u64_sum(a0[0][s]) + bq0;
                qox[s * 64 + lane + 32]  = u64_sum(a1[0][s]) + bq1;
                kbuf[s * 64 + lane]      = u64_sum(a0[1][s]) + bk0;
                kbuf[s * 64 + lane + 32] = u64_sum(a1[1][s]) + bk1;
                vbuf[s * 64 + lane]      = u64_sum(a0[2][s]) + bv0;
                vbuf[s * 64 + lane + 32] = u64_sum(a1[2][s]) + bv1;
            }
        }
        // fused k,v from xjff
        {
            uint64_t a0[2][4], a1[2][4];
            mmpM_core<4, 2>(xjff, 64, sWq, woff2, lane, a0, a1);
            float bk0 = sbq[64 + lane],  bk1 = sbq[64 + lane + 32];
            float bv0 = sbq[128 + lane], bv1 = sbq[128 + lane + 32];
#pragma unroll
            for (int s = 0; s < 4; s++) {
                kbuf[256 + s * 64 + lane]      = u64_sum(a0[0][s]) + bk0;
                kbuf[256 + s * 64 + lane + 32] = u64_sum(a1[0][s]) + bk1;
                vbuf[256 + s * 64 + lane]      = u64_sum(a0[1][s]) + bv0;
                vbuf[256 + s * 64 + lane + 32] = u64_sum(a1[1][s]) + bv1;
            }
        }
        __syncwarp();

        // attention: 16 active lanes = 4 heads x 4 query tokens; o in-place over q
        if (lane < 16) {
            const int h = lane >> 2, s = lane & 3;
            float q[16];
            const float* qp = qox + s * 64 + h * 16;
#pragma unroll
            for (int d = 0; d < 16; d++) q[d] = qp[d];
            float scr[8];
#pragma unroll
            for (int t = 0; t < 8; t++) {
                const float* kp = kbuf + t * 64 + h * 16;
                float a = 0.f;
#pragma unroll
                for (int d = 0; d < 16; d++) a = fmaf(q[d], kp[d], a);
                scr[t] = a * 0.25f;  // 1/sqrt(16)
            }
            float m = scr[0];
#pragma unroll
            for (int t = 1; t < 8; t++) m = fmaxf(m, scr[t]);
            float ssum = 0.f;
#pragma unroll
            for (int t = 0; t < 8; t++) { scr[t] = __expf(scr[t] - m); ssum += scr[t]; }
            float inv = 1.f / ssum;
            float o[16];
#pragma unroll
            for (int d = 0; d < 16; d++) o[d] = 0.f;
#pragma unroll
            for (int t = 0; t < 8; t++) {
                const float* vp = vbuf + t * 64 + h * 16;
                float p = scr[t] * inv;
#pragma unroll
                for (int d = 0; d < 16; d++) o[d] = fmaf(p, vp[d], o[d]);
            }
            float* op = qox + s * 64 + h * 16;   // in-place (own slice only)
#pragma unroll
            for (int d = 0; d < 16; d++) op[d] = o[d];
        }
        __syncwarp();

        // attn proj + residual(xi) + LN1; reads all of qox, then rewrites it
        {
            uint64_t a0[4], a1[4];
            mmp1_core<4>(qox, 64, sWo, lane, a0, a1);
            __syncwarp();
            float b0 = sbo[lane], b1 = sbo[lane + 32];
#pragma unroll
            for (int t = 0; t < 4; t++) {
                float r0 = u64_sum(a0[t]) + b0 + xi[t * 64 + lane];
                float r1 = u64_sum(a1[t]) + b1 + xi[t * 64 + lane + 32];
                float y0, y1;
                ln_pair(r0, r1, sg1, sbe1, lane, y0, y1);
                qox[t * 64 + lane]      = y0;
                qox[t * 64 + lane + 32] = y1;
            }
        }
        __syncwarp();

        // FF1 (relu): qox -> xjff
        {
            uint64_t a0[4], a1[4];
            mmp1_core<4>(qox, 64, sW1, lane, a0, a1);
            float b0 = sbf1[lane], b1 = sbf1[lane + 32];
#pragma unroll
            for (int s = 0; s < 4; s++) {
                xjff[s * 64 + lane]      = fmaxf(u64_sum(a0[s]) + b0, 0.f);
                xjff[s * 64 + lane + 32] = fmaxf(u64_sum(a1[s]) + b1, 0.f);
            }
        }
        __syncwarp();

        // FF2 + residual(qox) + LN2 -> vector atomic scatter (pair-interleaved layout:
        // g_acc position 2*lane <- channel lane, 2*lane+1 <- channel lane+32)
        {
            uint64_t a0[4], a1[4];
            mmp1_core<4>(xjff, 64, sW2, lane, a0, a1);
            float b0 = sbf2[lane], b1 = sbf2[lane + 32];
            float* accp = accbase + (size_t)dst * 256;
#pragma unroll
            for (int t = 0; t < 4; t++) {
                float r0 = u64_sum(a0[t]) + b0 + qox[t * 64 + lane];
                float r1 = u64_sum(a1[t]) + b1 + qox[t * 64 + lane + 32];
                float y0, y1;
                ln_pair(r0, r1, sg2, sbe2, lane, y0, y1);
                asm volatile("red.global.add.v2.f32 [%0], {%1, %2};"
                             :: "l"(accp + t * 64 + 2 * lane), "f"(y0), "f"(y1) : "memory");
            }
            if (lane == 0) atomicAdd(cntbase + dst, 1);
        }
        __syncwarp();
    }
}

// ---------------------------------------------------------------------------
// final: mean across edge types (un-permuting the pair-interleaved acc layout),
// Wout per token, sum over tokens, softmax(32). One warp per node.
// ---------------------------------------------------------------------------
__global__ void __launch_bounds__(128) out_kernel(const float* __restrict__ Wout,
                                                  const float* __restrict__ bout,
                                                  float* __restrict__ out) {
    __shared__ float sW[2048];   // [c][o]
    __shared__ float sb[32];
    __shared__ float comb[4][256];
    const int tid = threadIdx.x;
    for (int i = tid; i < 2048; i += 128) { int o = i >> 6, c = i & 63; sW[c * 32 + o] = Wout[i]; }
    if (tid < 32) sb[tid] = bout[tid];
    __syncthreads();

    const int warp = tid >> 5, lane = tid & 31;
    const int n = blockIdx.x * 4 + warp;
    if (n >= NA_N) return;

    const int c0 = g_cnt[n], c1 = g_cnt[NA_N + n];
    const float i0 = (c0 > 0) ? 0.5f / (float)c0 : 0.f;
    const float i1 = (c1 > 0) ? 0.5f / (float)c1 : 0.f;
    const float* a0 = g_acc + (size_t)n * 256;
    const float* a1 = g_acc + (size_t)NA_N * 256 + (size_t)n * 256;
    float* cb = comb[warp];
#pragma unroll
    for (int j = 0; j < 8; j++) {
        int i = lane + 32 * j;
        int t = i >> 6, p = i & 63;
        int c = ((p & 1) << 5) + (p >> 1);   // un-permute pair-interleaved channel
        cb[t * 64 + c] = a0[i] * i0 + a1[i] * i1;
    }
    __syncwarp();

    float h = 0.f;
#pragma unroll 4
    for (int i = 0; i < 256; i++) {
        int c = i & 63;
        h = fmaf(cb[i], sW[c * 32 + lane], h);
    }
    h += 4.f * sb[lane];

    float m = warp_max(h);
    float ex = __expf(h - m);
    float s = warp_sum(ex);
    out[(size_t)n * 32 + lane] = ex / s;
}

// ---------------------------------------------------------------------------
extern "C" void kernel_launch(void* const* d_in, const int* in_sizes, int n_in,
                              void* d_out, int out_size) {
    const float* xA   = (const float*)d_in[0];
    const float* xB   = (const float*)d_in[1];
    const int*   e0   = (const int*)d_in[2];
    const int*   e1   = (const int*)d_in[3];
    const float* Wb   = (const float*)d_in[4];
    const float* bb   = (const float*)d_in[5];
    const float* Wqkv = (const float*)d_in[6];
    const float* bqkv = (const float*)d_in[7];
    const float* Wo   = (const float*)d_in[8];
    const float* bo   = (const float*)d_in[9];
    const float* g1   = (const float*)d_in[10];
    const float* be1  = (const float*)d_in[11];
    const float* W1   = (const float*)d_in[12];
    const float* bf1  = (const float*)d_in[13];
    const float* W2   = (const float*)d_in[14];
    const float* bf2  = (const float*)d_in[15];
    const float* g2   = (const float*)d_in[16];
    const float* be2  = (const float*)d_in[17];
    const float* Wout = (const float*)d_in[18];
    const float* bout = (const float*)d_in[19];

    const int E0 = in_sizes[2] / 2;
    const int E1 = in_sizes[3] / 2;

    // weights (64+192+64+64+64)*WSTR = 448*68 = 30464 + biases 704 + 8*1792 = 45504 floats
    const int smem_bytes = (448 * WSTR + 704 + WARPS_PER_BLK * 1792) * 4;  // 182,016 B
    cudaFuncSetAttribute(edge_kernel, cudaFuncAttributeMaxDynamicSharedMemorySize, smem_bytes);

    zero_kernel<<<2048, 256>>>();
    edge_kernel<<<2 * EDGE_BLOCKS, THREADS_BLK, smem_bytes>>>(
        xA, xB, e0, E0, e1, E1,
        Wb, bb, Wqkv, bqkv, Wo, bo, g1, be1, W1, bf1, W2, bf2, g2, be2);
    out_kernel<<<(NA_N + 3) / 4, 128>>>(Wout, bout, (float*)d_out);
}

// round 6
// speedup vs baseline: 1.4294x; 1.4294x over previous
#include <cuda_runtime.h>
#include <math.h>
#include <stdint.h>

// Problem constants (fixed-shape problem)
#define NA_N   40000
#define NB_N   40000
#define EPS_LN 1e-5f

#define WARPS_PER_BLK 8
#define EDGE_BLOCKS   148          // per edge type
#define EDGE_STRIDE   (EDGE_BLOCKS * WARPS_PER_BLK)
#define THREADS_BLK   (WARPS_PER_BLK * 32)
#define NODE_STRIDE   (148 * WARPS_PER_BLK)

// Scratch (static device arrays; no runtime alloc)
__device__ float g_acc[2ull * NA_N * 256ull];
__device__ int   g_cnt[2 * NA_N];
// Precomputed per-(type,node) projections:
//   g_dstqkv[t][n][0:256)=q, [256:512)=k, [512:768)=v   (from xA, Wqkv[t])
//   g_srckv [t][n][0:256)=k, [256:512)=v                (from b_proj(x_src), Wqkv[t])
__device__ float g_dstqkv[2ull * NA_N * 768ull];
__device__ float g_srckv [2ull * NA_N * 512ull];

// ---------------------------------------------------------------------------
// helpers
// ---------------------------------------------------------------------------
__device__ __forceinline__ float warp_sum(float v) {
#pragma unroll
    for (int o = 16; o; o >>= 1) v += __shfl_xor_sync(0xffffffffu, v, o);
    return v;
}
__device__ __forceinline__ float warp_max(float v) {
#pragma unroll
    for (int o = 16; o; o >>= 1) v = fmaxf(v, __shfl_xor_sync(0xffffffffu, v, o));
    return v;
}

// Single-matrix GEMM core: out[s][f] partials over 64-dim reduction.
// Weights [c][f] in smem, lane owns (lane, lane+32) -> two LDS.32, conflict-free.
// Input rows read as broadcast float4 LDS.
template <int S>
__device__ __forceinline__ void mm64_core(const float* __restrict__ in, int in_stride,
                                          const float* __restrict__ Wt, int wstride,
                                          int lane, float* a0, float* a1) {
#pragma unroll
    for (int s = 0; s < S; s++) { a0[s] = 0.f; a1[s] = 0.f; }
#pragma unroll
    for (int c4 = 0; c4 < 16; c4++) {
        float4 xv[S];
#pragma unroll
        for (int s = 0; s < S; s++)
            xv[s] = *reinterpret_cast<const float4*>(in + s * in_stride + (c4 << 2));
#pragma unroll
        for (int j = 0; j < 4; j++) {
            const float* wrow = Wt + ((c4 << 2) + j) * wstride;
            float w0 = wrow[lane];
            float w1 = wrow[lane + 32];
#pragma unroll
            for (int s = 0; s < S; s++) {
                float xx = (j == 0) ? xv[s].x : (j == 1) ? xv[s].y : (j == 2) ? xv[s].z : xv[s].w;
                a0[s] = fmaf(xx, w0, a0[s]);
                a1[s] = fmaf(xx, w1, a1[s]);
            }
        }
    }
}

template <int S, bool RELU>
__device__ __forceinline__ void mm64_store(const float* __restrict__ in, int in_stride,
                                           const float* __restrict__ Wt, int wstride,
                                           const float* __restrict__ bias,
                                           float* __restrict__ out, int out_stride, int lane) {
    float a0[S], a1[S];
    mm64_core<S>(in, in_stride, Wt, wstride, lane, a0, a1);
    float b0 = bias[lane], b1 = bias[lane + 32];
#pragma unroll
    for (int s = 0; s < S; s++) {
        float r0 = a0[s] + b0, r1 = a1[s] + b1;
        if (RELU) { r0 = fmaxf(r0, 0.f); r1 = fmaxf(r1, 0.f); }
        out[s * out_stride + lane]      = r0;
        out[s * out_stride + lane + 32] = r1;
    }
}

// Fused multi-matrix sweep over sWq ([c][192] layout): M weight streams.
template <int M>
__device__ __forceinline__ void mmqkv_core(const float* __restrict__ in,
                                           const float* __restrict__ Wq, const int* woff,
                                           int lane, float (*a0)[4], float (*a1)[4]) {
#pragma unroll
    for (int m = 0; m < M; m++)
#pragma unroll
        for (int s = 0; s < 4; s++) { a0[m][s] = 0.f; a1[m][s] = 0.f; }
#pragma unroll
    for (int c4 = 0; c4 < 16; c4++) {
        float4 xv[4];
#pragma unroll
        for (int s = 0; s < 4; s++)
            xv[s] = *reinterpret_cast<const float4*>(in + s * 64 + (c4 << 2));
#pragma unroll
        for (int j = 0; j < 4; j++) {
            const float* wrow = Wq + ((c4 << 2) + j) * 192;
            float w0[M], w1[M];
#pragma unroll
            for (int m = 0; m < M; m++) {
                w0[m] = wrow[woff[m] + lane];
                w1[m] = wrow[woff[m] + lane + 32];
            }
#pragma unroll
            for (int s = 0; s < 4; s++) {
                float xx = (j == 0) ? xv[s].x : (j == 1) ? xv[s].y : (j == 2) ? xv[s].z : xv[s].w;
#pragma unroll
                for (int m = 0; m < M; m++) {
                    a0[m][s] = fmaf(xx, w0[m], a0[m][s]);
                    a1[m][s] = fmaf(xx, w1[m], a1[m][s]);
                }
            }
        }
    }
}

// LayerNorm over 64 features distributed as (lane, lane+32).
__device__ __forceinline__ void ln_pair(float r0, float r1,
                                        const float* __restrict__ g, const float* __restrict__ b,
                                        int lane, float& y0, float& y1) {
    float m = warp_sum(r0 + r1) * (1.f / 64.f);
    float d0 = r0 - m, d1 = r1 - m;
    float v = warp_sum(d0 * d0 + d1 * d1) * (1.f / 64.f);
    float inv = rsqrtf(v + EPS_LN);
    y0 = d0 * inv * g[lane]      + b[lane];
    y1 = d1 * inv * g[lane + 32] + b[lane + 32];
}

// ---------------------------------------------------------------------------
// zero scratch
// ---------------------------------------------------------------------------
__global__ void zero_kernel() {
    size_t i = (size_t)blockIdx.x * blockDim.x + threadIdx.x;
    size_t stride = (size_t)gridDim.x * blockDim.x;
    float4* p = reinterpret_cast<float4*>(g_acc);
    size_t n4 = (2ull * NA_N * 256ull) / 4;
    for (size_t j = i; j < n4; j += stride) p[j] = make_float4(0.f, 0.f, 0.f, 0.f);
    for (size_t j = i; j < 2 * NA_N; j += stride) g_cnt[j] = 0;
}

// ---------------------------------------------------------------------------
// Precompute per-(type, A-node): q,k,v of the dst tokens. One warp per node.
// ---------------------------------------------------------------------------
__global__ void __launch_bounds__(THREADS_BLK, 1) dstpre_kernel(
    const float* __restrict__ xA,
    const float* __restrict__ Wqkv, const float* __restrict__ bqkv) {
    extern __shared__ float smem[];
    float* sWq = smem;            // [c][192]
    float* sbq = sWq + 12288;     // 192
    float* bufs = sbq + 192;      // 8 warps * 256

    const int type = blockIdx.x & 1;
    const int bidx = blockIdx.x >> 1;
    const int tid = threadIdx.x;
    {
        const float* p = Wqkv + type * 12288;
        for (int i = tid; i < 12288; i += THREADS_BLK) { int g = i >> 6, c = i & 63; sWq[c * 192 + g] = p[i]; }
        if (tid < 192) sbq[tid] = bqkv[type * 192 + tid];
    }
    __syncthreads();

    const int warp = tid >> 5, lane = tid & 31;
    float* buf = bufs + warp * 256;
    const int woff3[3] = {0, 64, 128};

    for (int n = bidx * WARPS_PER_BLK + warp; n < NA_N; n += NODE_STRIDE) {
        const float4* gx = reinterpret_cast<const float4*>(xA + (size_t)n * 256);
        reinterpret_cast<float4*>(buf)[lane]      = __ldg(gx + lane);
        reinterpret_cast<float4*>(buf)[lane + 32] = __ldg(gx + lane + 32);
        __syncwarp();
        float a0[3][4], a1[3][4];
        mmqkv_core<3>(buf, sWq, woff3, lane, a0, a1);
        float* outp = g_dstqkv + ((size_t)type * NA_N + n) * 768;
#pragma unroll
        for (int m = 0; m < 3; m++) {
            float b0 = sbq[woff3[m] + lane], b1 = sbq[woff3[m] + lane + 32];
#pragma unroll
            for (int s = 0; s < 4; s++) {
                outp[m * 256 + s * 64 + lane]      = a0[m][s] + b0;
                outp[m * 256 + s * 64 + lane + 32] = a1[m][s] + b1;
            }
        }
        __syncwarp();
    }
}

// ---------------------------------------------------------------------------
// Precompute per-(type, src-node): xj = b_proj(x_src), then its k,v.
// ---------------------------------------------------------------------------
__global__ void __launch_bounds__(THREADS_BLK, 1) srcpre_kernel(
    const float* __restrict__ xA, const float* __restrict__ xB,
    const float* __restrict__ Wb, const float* __restrict__ bb,
    const float* __restrict__ Wqkv, const float* __restrict__ bqkv) {
    extern __shared__ float smem[];
    float* sWb = smem;            // [c][64]
    float* sWq = sWb + 4096;      // [c][192]
    float* sbb = sWq + 12288;     // 64
    float* sbq = sbb + 64;        // 192
    float* bufs = sbq + 192;      // 8 warps * 256

    const int type = blockIdx.x & 1;
    const int bidx = blockIdx.x >> 1;
    const int tid = threadIdx.x;
    {
        const float* p = Wb + type * 4096;
        for (int i = tid; i < 4096; i += THREADS_BLK)  { int f = i >> 6, c = i & 63; sWb[c * 64 + f] = p[i]; }
        p = Wqkv + type * 12288;
        for (int i = tid; i < 12288; i += THREADS_BLK) { int g = i >> 6, c = i & 63; sWq[c * 192 + g] = p[i]; }
        if (tid < 64)  sbb[tid] = bb[type * 64 + tid];
        if (tid < 192) sbq[tid] = bqkv[type * 192 + tid];
    }
    __syncthreads();

    const int warp = tid >> 5, lane = tid & 31;
    float* buf = bufs + warp * 256;
    const float* xsrc = type ? xA : xB;
    const int NSRC = NA_N;   // both node sets are 40000
    const int woff2[2] = {64, 128};

    for (int n = bidx * WARPS_PER_BLK + warp; n < NSRC; n += NODE_STRIDE) {
        const float4* gx = reinterpret_cast<const float4*>(xsrc + (size_t)n * 256);
        reinterpret_cast<float4*>(buf)[lane]      = __ldg(gx + lane);
        reinterpret_cast<float4*>(buf)[lane + 32] = __ldg(gx + lane + 32);
        __syncwarp();
        // xj = b_proj(x): all reads of buf complete before overwrite (results in regs)
        {
            float a0[4], a1[4];
            mm64_core<4>(buf, 64, sWb, 64, lane, a0, a1);
            __syncwarp();
            float b0 = sbb[lane], b1 = sbb[lane + 32];
#pragma unroll
            for (int s = 0; s < 4; s++) {
                buf[s * 64 + lane]      = a0[s] + b0;
                buf[s * 64 + lane + 32] = a1[s] + b1;
            }
        }
        __syncwarp();
        float a0[2][4], a1[2][4];
        mmqkv_core<2>(buf, sWq, woff2, lane, a0, a1);
        float* outp = g_srckv + ((size_t)type * NA_N + n) * 512;
#pragma unroll
        for (int m = 0; m < 2; m++) {
            float b0 = sbq[woff2[m] + lane], b1 = sbq[woff2[m] + lane + 32];
#pragma unroll
            for (int s = 0; s < 4; s++) {
                outp[m * 256 + s * 64 + lane]      = a0[m][s] + b0;
                outp[m * 256 + s * 64 + lane + 32] = a1[m][s] + b1;
            }
        }
        __syncwarp();
    }
}

// ---------------------------------------------------------------------------
// per-edge: gather precomputed q/k/v + xi, attention, Wo+LN1, FFN+LN2, scatter.
// One warp = one edge. Per-warp smem (1792 floats):
//   xi[256] | xjff[256] | qox[256] | k[512] | v[512]
// ---------------------------------------------------------------------------
__global__ void __launch_bounds__(THREADS_BLK, 1) edge_kernel(
    const float* __restrict__ xA,
    const int* __restrict__ e0, int E0,
    const int* __restrict__ e1, int E1,
    const float* __restrict__ Wo,  const float* __restrict__ bo,
    const float* __restrict__ g1,  const float* __restrict__ be1,
    const float* __restrict__ W1,  const float* __restrict__ bf1,
    const float* __restrict__ W2,  const float* __restrict__ bf2,
    const float* __restrict__ g2,  const float* __restrict__ be2) {
    extern __shared__ float smem[];
    float* sWo  = smem;              // [c][f]  64*64
    float* sW1  = sWo + 4096;        // [c][f]  64*64
    float* sW2  = sW1 + 4096;        // [f][c]  64*64
    float* sbo  = sW2 + 4096;        // 64
    float* sbf1 = sbo + 64;
    float* sbf2 = sbf1 + 64;
    float* sg1  = sbf2 + 64;
    float* sbe1 = sg1 + 64;
    float* sg2  = sbe1 + 64;
    float* sbe2 = sg2 + 64;
    float* bufs = sbe2 + 64;         // 8 warps * 1792

    const int type = blockIdx.x & 1;
    const int bidx = blockIdx.x >> 1;
    const int tid = threadIdx.x;
    {
        const float* p = Wo + type * 4096;
        for (int i = tid; i < 4096; i += THREADS_BLK) { int f = i >> 6, c = i & 63; sWo[c * 64 + f] = p[i]; }
        p = W1 + type * 4096;
        for (int i = tid; i < 4096; i += THREADS_BLK) { int f = i >> 6, c = i & 63; sW1[c * 64 + f] = p[i]; }
        p = W2 + type * 4096;
        for (int i = tid; i < 4096; i += THREADS_BLK) { int c = i >> 6, f = i & 63; sW2[f * 64 + c] = p[i]; }
        if (tid < 64) sbo[tid]  = bo[type * 64 + tid];
        if (tid < 64) sbf1[tid] = bf1[type * 64 + tid];
        if (tid < 64) sbf2[tid] = bf2[type * 64 + tid];
        if (tid < 64) sg1[tid]  = g1[type * 64 + tid];
        if (tid < 64) sbe1[tid] = be1[type * 64 + tid];
        if (tid < 64) sg2[tid]  = g2[type * 64 + tid];
        if (tid < 64) sbe2[tid] = be2[type * 64 + tid];
    }
    __syncthreads();

    const int warp = tid >> 5, lane = tid & 31;
    float* xi   = bufs + warp * 1792;
    float* xjff = xi + 256;
    float* qox  = xjff + 256;
    float* kbuf = qox + 256;
    float* vbuf = kbuf + 512;

    const int* ei = type ? e1 : e0;
    const int  E  = type ? E1 : E0;
    float* accbase = g_acc + (size_t)type * NA_N * 256ull;
    int*   cntbase = g_cnt + type * NA_N;

    for (int e = bidx * WARPS_PER_BLK + warp; e < E; e += EDGE_STRIDE) {
        const int src = __ldg(ei + e);
        const int dst = __ldg(ei + E + e);

        // Gather xi + precomputed q/k/v(dst) + k/v(src): 12 independent LDG.128/lane
        {
            const float4* gxi = reinterpret_cast<const float4*>(xA + (size_t)dst * 256);
            const float4* gdq = reinterpret_cast<const float4*>(g_dstqkv + ((size_t)type * NA_N + dst) * 768);
            const float4* gsk = reinterpret_cast<const float4*>(g_srckv  + ((size_t)type * NA_N + src) * 512);
            float4 t0 = __ldg(gxi + lane);
            float4 t1 = __ldg(gxi + lane + 32);
            float4 t2 = __ldg(gdq + lane);         // q
            float4 t3 = __ldg(gdq + lane + 32);
            float4 t4 = __ldg(gdq + 64 + lane);    // k(dst)
            float4 t5 = __ldg(gdq + 64 + lane + 32);
            float4 t6 = __ldg(gdq + 128 + lane);   // v(dst)
            float4 t7 = __ldg(gdq + 128 + lane + 32);
            float4 t8 = __ldg(gsk + lane);         // k(src)
            float4 t9 = __ldg(gsk + lane + 32);
            float4 ta = __ldg(gsk + 64 + lane);    // v(src)
            float4 tb = __ldg(gsk + 64 + lane + 32);
            reinterpret_cast<float4*>(xi)[lane]          = t0;
            reinterpret_cast<float4*>(xi)[lane + 32]     = t1;
            reinterpret_cast<float4*>(qox)[lane]         = t2;
            reinterpret_cast<float4*>(qox)[lane + 32]    = t3;
            reinterpret_cast<float4*>(kbuf)[lane]        = t4;
            reinterpret_cast<float4*>(kbuf)[lane + 32]   = t5;
            reinterpret_cast<float4*>(vbuf)[lane]        = t6;
            reinterpret_cast<float4*>(vbuf)[lane + 32]   = t7;
            reinterpret_cast<float4*>(kbuf + 256)[lane]      = t8;
            reinterpret_cast<float4*>(kbuf + 256)[lane + 32] = t9;
            reinterpret_cast<float4*>(vbuf + 256)[lane]      = ta;
            reinterpret_cast<float4*>(vbuf + 256)[lane + 32] = tb;
        }
        __syncwarp();

        // attention: 16 active lanes = 4 heads x 4 query tokens; o in-place over q
        if (lane < 16) {
            const int h = lane >> 2, s = lane & 3;
            float q[16];
            const float* qp = qox + s * 64 + h * 16;
#pragma unroll
            for (int d = 0; d < 16; d++) q[d] = qp[d];
            float scr[8];
#pragma unroll
            for (int t = 0; t < 8; t++) {
                const float* kp = kbuf + t * 64 + h * 16;
                float a = 0.f;
#pragma unroll
                for (int d = 0; d < 16; d++) a = fmaf(q[d], kp[d], a);
                scr[t] = a * 0.25f;  // 1/sqrt(16)
            }
            float m = scr[0];
#pragma unroll
            for (int t = 1; t < 8; t++) m = fmaxf(m, scr[t]);
            float ssum = 0.f;
#pragma unroll
            for (int t = 0; t < 8; t++) { scr[t] = __expf(scr[t] - m); ssum += scr[t]; }
            float inv = 1.f / ssum;
            float o[16];
#pragma unroll
            for (int d = 0; d < 16; d++) o[d] = 0.f;
#pragma unroll
            for (int t = 0; t < 8; t++) {
                const float* vp = vbuf + t * 64 + h * 16;
                float p = scr[t] * inv;
#pragma unroll
                for (int d = 0; d < 16; d++) o[d] = fmaf(p, vp[d], o[d]);
            }
            float* op = qox + s * 64 + h * 16;   // in-place (own slice only)
#pragma unroll
            for (int d = 0; d < 16; d++) op[d] = o[d];
        }
        __syncwarp();

        // attn proj + residual(xi) + LN1; reads all of qox, then rewrites it
        {
            float a0[4], a1[4];
            mm64_core<4>(qox, 64, sWo, 64, lane, a0, a1);
            __syncwarp();
            float b0 = sbo[lane], b1 = sbo[lane + 32];
#pragma unroll
            for (int t = 0; t < 4; t++) {
                float r0 = a0[t] + b0 + xi[t * 64 + lane];
                float r1 = a1[t] + b1 + xi[t * 64 + lane + 32];
                float y0, y1;
                ln_pair(r0, r1, sg1, sbe1, lane, y0, y1);
                qox[t * 64 + lane]      = y0;
                qox[t * 64 + lane + 32] = y1;
            }
        }
        __syncwarp();

        // FF1 (relu): qox -> xjff
        mm64_store<4, true>(qox, 64, sW1, 64, sbf1, xjff, 64, lane);
        __syncwarp();

        // FF2 + residual(qox) + LN2 -> atomic scatter
        {
            float a0[4], a1[4];
            mm64_core<4>(xjff, 64, sW2, 64, lane, a0, a1);
            float b0 = sbf2[lane], b1 = sbf2[lane + 32];
            float* accp = accbase + (size_t)dst * 256;
#pragma unroll
            for (int t = 0; t < 4; t++) {
                float r0 = a0[t] + b0 + qox[t * 64 + lane];
                float r1 = a1[t] + b1 + qox[t * 64 + lane + 32];
                float y0, y1;
                ln_pair(r0, r1, sg2, sbe2, lane, y0, y1);
                atomicAdd(accp + t * 64 + lane, y0);
                atomicAdd(accp + t * 64 + lane + 32, y1);
            }
            if (lane == 0) atomicAdd(cntbase + dst, 1);
        }
        __syncwarp();
    }
}

// ---------------------------------------------------------------------------
// final: mean across edge types, Wout per token, sum over tokens, softmax(32)
// one warp per node, 4 nodes per block
// ---------------------------------------------------------------------------
__global__ void __launch_bounds__(128) out_kernel(const float* __restrict__ Wout,
                                                  const float* __restrict__ bout,
                                                  float* __restrict__ out) {
    __shared__ float sW[2048];   // [c][o]
    __shared__ float sb[32];
    __shared__ float comb[4][256];
    const int tid = threadIdx.x;
    for (int i = tid; i < 2048; i += 128) { int o = i >> 6, c = i & 63; sW[c * 32 + o] = Wout[i]; }
    if (tid < 32) sb[tid] = bout[tid];
    __syncthreads();

    const int warp = tid >> 5, lane = tid & 31;
    const int n = blockIdx.x * 4 + warp;
    if (n >= NA_N) return;

    const int c0 = g_cnt[n], c1 = g_cnt[NA_N + n];
    const float i0 = (c0 > 0) ? 0.5f / (float)c0 : 0.f;
    const float i1 = (c1 > 0) ? 0.5f / (float)c1 : 0.f;
    const float* a0 = g_acc + (size_t)n * 256;
    const float* a1 = g_acc + (size_t)NA_N * 256 + (size_t)n * 256;
    float* cb = comb[warp];
#pragma unroll
    for (int j = 0; j < 8; j++) {
        int i = lane + 32 * j;
        cb[i] = a0[i] * i0 + a1[i] * i1;
    }
    __syncwarp();

    float h = 0.f;
#pragma unroll 4
    for (int i = 0; i < 256; i++) {
        int c = i & 63;
        h = fmaf(cb[i], sW[c * 32 + lane], h);
    }
    h += 4.f * sb[lane];

    float m = warp_max(h);
    float ex = __expf(h - m);
    float s = warp_sum(ex);
    out[(size_t)n * 32 + lane] = ex / s;
}

// ---------------------------------------------------------------------------
extern "C" void kernel_launch(void* const* d_in, const int* in_sizes, int n_in,
                              void* d_out, int out_size) {
    const float* xA   = (const float*)d_in[0];
    const float* xB   = (const float*)d_in[1];
    const int*   e0   = (const int*)d_in[2];
    const int*   e1   = (const int*)d_in[3];
    const float* Wb   = (const float*)d_in[4];
    const float* bb   = (const float*)d_in[5];
    const float* Wqkv = (const float*)d_in[6];
    const float* bqkv = (const float*)d_in[7];
    const float* Wo   = (const float*)d_in[8];
    const float* bo   = (const float*)d_in[9];
    const float* g1   = (const float*)d_in[10];
    const float* be1  = (const float*)d_in[11];
    const float* W1   = (const float*)d_in[12];
    const float* bf1  = (const float*)d_in[13];
    const float* W2   = (const float*)d_in[14];
    const float* bf2  = (const float*)d_in[15];
    const float* g2   = (const float*)d_in[16];
    const float* be2  = (const float*)d_in[17];
    const float* Wout = (const float*)d_in[18];
    const float* bout = (const float*)d_in[19];

    const int E0 = in_sizes[2] / 2;
    const int E1 = in_sizes[3] / 2;

    const int dst_smem  = (12288 + 192 + WARPS_PER_BLK * 256) * 4;                  // 58,112 B
    const int src_smem  = (4096 + 12288 + 64 + 192 + WARPS_PER_BLK * 256) * 4;      // 74,752 B
    const int edge_smem = (3 * 4096 + 7 * 64 + WARPS_PER_BLK * 1792) * 4;           // 108,288 B
    cudaFuncSetAttribute(dstpre_kernel, cudaFuncAttributeMaxDynamicSharedMemorySize, dst_smem);
    cudaFuncSetAttribute(srcpre_kernel, cudaFuncAttributeMaxDynamicSharedMemorySize, src_smem);
    cudaFuncSetAttribute(edge_kernel,   cudaFuncAttributeMaxDynamicSharedMemorySize, edge_smem);

    zero_kernel<<<2048, 256>>>();
    dstpre_kernel<<<2 * 148, THREADS_BLK, dst_smem>>>(xA, Wqkv, bqkv);
    srcpre_kernel<<<2 * 148, THREADS_BLK, src_smem>>>(xA, xB, Wb, bb, Wqkv, bqkv);
    edge_kernel<<<2 * EDGE_BLOCKS, THREADS_BLK, edge_smem>>>(
        xA, e0, E0, e1, E1,
        Wo, bo, g1, be1, W1, bf1, W2, bf2, g2, be2);
    out_kernel<<<(NA_N + 3) / 4, 128>>>(Wout, bout, (float*)d_out);
}

// round 7
// speedup vs baseline: 1.4817x; 1.0366x over previous
#include <cuda_runtime.h>
#include <math.h>
#include <stdint.h>

// Problem constants (fixed-shape problem)
#define NA_N   40000
#define NB_N   40000
#define EPS_LN 1e-5f

#define WARPS_PER_BLK 10
#define EDGE_BLOCKS   148          // per edge type
#define THREADS_BLK   (WARPS_PER_BLK * 32)
#define PAIR_STRIDE   (EDGE_BLOCKS * WARPS_PER_BLK * 2)
#define NODE_STRIDE   (148 * WARPS_PER_BLK)

// Scratch (static device arrays; no runtime alloc)
__device__ float g_acc[2ull * NA_N * 256ull];
__device__ int   g_cnt[2 * NA_N];
// Precomputed per-(type,node) projections:
//   g_dstqkv[t][n][0:256)=q, [256:512)=k, [512:768)=v   (from xA, Wqkv[t])
//   g_srckv [t][n][0:256)=k, [256:512)=v                (from b_proj(x_src), Wqkv[t])
__device__ float g_dstqkv[2ull * NA_N * 768ull];
__device__ float g_srckv [2ull * NA_N * 512ull];

// ---------------------------------------------------------------------------
// helpers
// ---------------------------------------------------------------------------
__device__ __forceinline__ float warp_sum(float v) {
#pragma unroll
    for (int o = 16; o; o >>= 1) v += __shfl_xor_sync(0xffffffffu, v, o);
    return v;
}
__device__ __forceinline__ float warp_max(float v) {
#pragma unroll
    for (int o = 16; o; o >>= 1) v = fmaxf(v, __shfl_xor_sync(0xffffffffu, v, o));
    return v;
}

// Single-matrix GEMM core: out[s][f] partials over 64-dim reduction.
// Weights [c][f] in smem, lane owns (lane, lane+32) -> two LDS.32, conflict-free.
// Input rows read as broadcast float4 LDS.
template <int S>
__device__ __forceinline__ void mm64_core(const float* __restrict__ in, int in_stride,
                                          const float* __restrict__ Wt, int wstride,
                                          int lane, float* a0, float* a1) {
#pragma unroll
    for (int s = 0; s < S; s++) { a0[s] = 0.f; a1[s] = 0.f; }
#pragma unroll
    for (int c4 = 0; c4 < 16; c4++) {
        float4 xv[S];
#pragma unroll
        for (int s = 0; s < S; s++)
            xv[s] = *reinterpret_cast<const float4*>(in + s * in_stride + (c4 << 2));
#pragma unroll
        for (int j = 0; j < 4; j++) {
            const float* wrow = Wt + ((c4 << 2) + j) * wstride;
            float w0 = wrow[lane];
            float w1 = wrow[lane + 32];
#pragma unroll
            for (int s = 0; s < S; s++) {
                float xx = (j == 0) ? xv[s].x : (j == 1) ? xv[s].y : (j == 2) ? xv[s].z : xv[s].w;
                a0[s] = fmaf(xx, w0, a0[s]);
                a1[s] = fmaf(xx, w1, a1[s]);
            }
        }
    }
}

template <int S, bool RELU>
__device__ __forceinline__ void mm64_store(const float* __restrict__ in, int in_stride,
                                           const float* __restrict__ Wt, int wstride,
                                           const float* __restrict__ bias,
                                           float* __restrict__ out, int out_stride, int lane) {
    float a0[S], a1[S];
    mm64_core<S>(in, in_stride, Wt, wstride, lane, a0, a1);
    float b0 = bias[lane], b1 = bias[lane + 32];
#pragma unroll
    for (int s = 0; s < S; s++) {
        float r0 = a0[s] + b0, r1 = a1[s] + b1;
        if (RELU) { r0 = fmaxf(r0, 0.f); r1 = fmaxf(r1, 0.f); }
        out[s * out_stride + lane]      = r0;
        out[s * out_stride + lane + 32] = r1;
    }
}

// Fused multi-matrix sweep over sWq ([c][192] layout): M weight streams.
template <int M>
__device__ __forceinline__ void mmqkv_core(const float* __restrict__ in,
                                           const float* __restrict__ Wq, const int* woff,
                                           int lane, float (*a0)[4], float (*a1)[4]) {
#pragma unroll
    for (int m = 0; m < M; m++)
#pragma unroll
        for (int s = 0; s < 4; s++) { a0[m][s] = 0.f; a1[m][s] = 0.f; }
#pragma unroll
    for (int c4 = 0; c4 < 16; c4++) {
        float4 xv[4];
#pragma unroll
        for (int s = 0; s < 4; s++)
            xv[s] = *reinterpret_cast<const float4*>(in + s * 64 + (c4 << 2));
#pragma unroll
        for (int j = 0; j < 4; j++) {
            const float* wrow = Wq + ((c4 << 2) + j) * 192;
            float w0[M], w1[M];
#pragma unroll
            for (int m = 0; m < M; m++) {
                w0[m] = wrow[woff[m] + lane];
                w1[m] = wrow[woff[m] + lane + 32];
            }
#pragma unroll
            for (int s = 0; s < 4; s++) {
                float xx = (j == 0) ? xv[s].x : (j == 1) ? xv[s].y : (j == 2) ? xv[s].z : xv[s].w;
#pragma unroll
                for (int m = 0; m < M; m++) {
                    a0[m][s] = fmaf(xx, w0[m], a0[m][s]);
                    a1[m][s] = fmaf(xx, w1[m], a1[m][s]);
                }
            }
        }
    }
}

// LayerNorm over 64 features distributed as (lane, lane+32).
__device__ __forceinline__ void ln_pair(float r0, float r1,
                                        const float* __restrict__ g, const float* __restrict__ b,
                                        int lane, float& y0, float& y1) {
    float m = warp_sum(r0 + r1) * (1.f / 64.f);
    float d0 = r0 - m, d1 = r1 - m;
    float v = warp_sum(d0 * d0 + d1 * d1) * (1.f / 64.f);
    float inv = rsqrtf(v + EPS_LN);
    y0 = d0 * inv * g[lane]      + b[lane];
    y1 = d1 * inv * g[lane + 32] + b[lane + 32];
}

// ---------------------------------------------------------------------------
// zero scratch
// ---------------------------------------------------------------------------
__global__ void zero_kernel() {
    size_t i = (size_t)blockIdx.x * blockDim.x + threadIdx.x;
    size_t stride = (size_t)gridDim.x * blockDim.x;
    float4* p = reinterpret_cast<float4*>(g_acc);
    size_t n4 = (2ull * NA_N * 256ull) / 4;
    for (size_t j = i; j < n4; j += stride) p[j] = make_float4(0.f, 0.f, 0.f, 0.f);
    for (size_t j = i; j < 2 * NA_N; j += stride) g_cnt[j] = 0;
}

// ---------------------------------------------------------------------------
// Precompute per-(type, A-node): q,k,v of the dst tokens. One warp per node.
// ---------------------------------------------------------------------------
__global__ void __launch_bounds__(THREADS_BLK, 1) dstpre_kernel(
    const float* __restrict__ xA,
    const float* __restrict__ Wqkv, const float* __restrict__ bqkv) {
    extern __shared__ float smem[];
    float* sWq = smem;            // [c][192]
    float* sbq = sWq + 12288;     // 192
    float* bufs = sbq + 192;      // WARPS * 256

    const int type = blockIdx.x & 1;
    const int bidx = blockIdx.x >> 1;
    const int tid = threadIdx.x;
    {
        const float* p = Wqkv + type * 12288;
        for (int i = tid; i < 12288; i += THREADS_BLK) { int g = i >> 6, c = i & 63; sWq[c * 192 + g] = p[i]; }
        if (tid < 192) sbq[tid] = bqkv[type * 192 + tid];
    }
    __syncthreads();

    const int warp = tid >> 5, lane = tid & 31;
    float* buf = bufs + warp * 256;
    const int woff3[3] = {0, 64, 128};

    for (int n = bidx * WARPS_PER_BLK + warp; n < NA_N; n += NODE_STRIDE) {
        const float4* gx = reinterpret_cast<const float4*>(xA + (size_t)n * 256);
        reinterpret_cast<float4*>(buf)[lane]      = __ldg(gx + lane);
        reinterpret_cast<float4*>(buf)[lane + 32] = __ldg(gx + lane + 32);
        __syncwarp();
        float a0[3][4], a1[3][4];
        mmqkv_core<3>(buf, sWq, woff3, lane, a0, a1);
        float* outp = g_dstqkv + ((size_t)type * NA_N + n) * 768;
#pragma unroll
        for (int m = 0; m < 3; m++) {
            float b0 = sbq[woff3[m] + lane], b1 = sbq[woff3[m] + lane + 32];
#pragma unroll
            for (int s = 0; s < 4; s++) {
                outp[m * 256 + s * 64 + lane]      = a0[m][s] + b0;
                outp[m * 256 + s * 64 + lane + 32] = a1[m][s] + b1;
            }
        }
        __syncwarp();
    }
}

// ---------------------------------------------------------------------------
// Precompute per-(type, src-node): xj = b_proj(x_src), then its k,v.
// ---------------------------------------------------------------------------
__global__ void __launch_bounds__(THREADS_BLK, 1) srcpre_kernel(
    const float* __restrict__ xA, const float* __restrict__ xB,
    const float* __restrict__ Wb, const float* __restrict__ bb,
    const float* __restrict__ Wqkv, const float* __restrict__ bqkv) {
    extern __shared__ float smem[];
    float* sWb = smem;            // [c][64]
    float* sWq = sWb + 4096;      // [c][192]
    float* sbb = sWq + 12288;     // 64
    float* sbq = sbb + 64;        // 192
    float* bufs = sbq + 192;      // WARPS * 256

    const int type = blockIdx.x & 1;
    const int bidx = blockIdx.x >> 1;
    const int tid = threadIdx.x;
    {
        const float* p = Wb + type * 4096;
        for (int i = tid; i < 4096; i += THREADS_BLK)  { int f = i >> 6, c = i & 63; sWb[c * 64 + f] = p[i]; }
        p = Wqkv + type * 12288;
        for (int i = tid; i < 12288; i += THREADS_BLK) { int g = i >> 6, c = i & 63; sWq[c * 192 + g] = p[i]; }
        if (tid < 64)  sbb[tid] = bb[type * 64 + tid];
        if (tid < 192) sbq[tid] = bqkv[type * 192 + tid];
    }
    __syncthreads();

    const int warp = tid >> 5, lane = tid & 31;
    float* buf = bufs + warp * 256;
    const float* xsrc = type ? xA : xB;
    const int NSRC = NA_N;   // both node sets are 40000
    const int woff2[2] = {64, 128};

    for (int n = bidx * WARPS_PER_BLK + warp; n < NSRC; n += NODE_STRIDE) {
        const float4* gx = reinterpret_cast<const float4*>(xsrc + (size_t)n * 256);
        reinterpret_cast<float4*>(buf)[lane]      = __ldg(gx + lane);
        reinterpret_cast<float4*>(buf)[lane + 32] = __ldg(gx + lane + 32);
        __syncwarp();
        {
            float a0[4], a1[4];
            mm64_core<4>(buf, 64, sWb, 64, lane, a0, a1);
            __syncwarp();
            float b0 = sbb[lane], b1 = sbb[lane + 32];
#pragma unroll
            for (int s = 0; s < 4; s++) {
                buf[s * 64 + lane]      = a0[s] + b0;
                buf[s * 64 + lane + 32] = a1[s] + b1;
            }
        }
        __syncwarp();
        float a0[2][4], a1[2][4];
        mmqkv_core<2>(buf, sWq, woff2, lane, a0, a1);
        float* outp = g_srckv + ((size_t)type * NA_N + n) * 512;
#pragma unroll
        for (int m = 0; m < 2; m++) {
            float b0 = sbq[woff2[m] + lane], b1 = sbq[woff2[m] + lane + 32];
#pragma unroll
            for (int s = 0; s < 4; s++) {
                outp[m * 256 + s * 64 + lane]      = a0[m][s] + b0;
                outp[m * 256 + s * 64 + lane + 32] = a1[m][s] + b1;
            }
        }
        __syncwarp();
    }
}

// ---------------------------------------------------------------------------
// per-edge: TWO edges per warp. Gather precomputed k/v, attention (32 lanes =
// 2 edges x 4 heads x 4 tokens, q straight from global), Wo+LN1, FFN+LN2,
// scatter. Per-warp smem (3072 floats):
//   qox[512 = 2x256] | kbuf[1024 = 2x(dst256|src256)] | vbuf[1024] | ffb[512]
// Token index t in 0..7: edge = t>>2, local token = t&3.
// ---------------------------------------------------------------------------
__global__ void __launch_bounds__(THREADS_BLK, 1) edge_kernel(
    const float* __restrict__ xA,
    const int* __restrict__ e0, int E0,
    const int* __restrict__ e1, int E1,
    const float* __restrict__ Wo,  const float* __restrict__ bo,
    const float* __restrict__ g1,  const float* __restrict__ be1,
    const float* __restrict__ W1,  const float* __restrict__ bf1,
    const float* __restrict__ W2,  const float* __restrict__ bf2,
    const float* __restrict__ g2,  const float* __restrict__ be2) {
    extern __shared__ float smem[];
    float* sWo  = smem;              // [c][f]  64*64
    float* sW1  = sWo + 4096;        // [c][f]  64*64
    float* sW2  = sW1 + 4096;        // [f][c]  64*64
    float* sbo  = sW2 + 4096;        // 64
    float* sbf1 = sbo + 64;
    float* sbf2 = sbf1 + 64;
    float* sg1  = sbf2 + 64;
    float* sbe1 = sg1 + 64;
    float* sg2  = sbe1 + 64;
    float* sbe2 = sg2 + 64;
    float* bufs = sbe2 + 64;         // WARPS * 3072

    const int type = blockIdx.x & 1;
    const int bidx = blockIdx.x >> 1;
    const int tid = threadIdx.x;
    {
        const float* p = Wo + type * 4096;
        for (int i = tid; i < 4096; i += THREADS_BLK) { int f = i >> 6, c = i & 63; sWo[c * 64 + f] = p[i]; }
        p = W1 + type * 4096;
        for (int i = tid; i < 4096; i += THREADS_BLK) { int f = i >> 6, c = i & 63; sW1[c * 64 + f] = p[i]; }
        p = W2 + type * 4096;
        for (int i = tid; i < 4096; i += THREADS_BLK) { int c = i >> 6, f = i & 63; sW2[f * 64 + c] = p[i]; }
        if (tid < 64) sbo[tid]  = bo[type * 64 + tid];
        if (tid < 64) sbf1[tid] = bf1[type * 64 + tid];
        if (tid < 64) sbf2[tid] = bf2[type * 64 + tid];
        if (tid < 64) sg1[tid]  = g1[type * 64 + tid];
        if (tid < 64) sbe1[tid] = be1[type * 64 + tid];
        if (tid < 64) sg2[tid]  = g2[type * 64 + tid];
        if (tid < 64) sbe2[tid] = be2[type * 64 + tid];
        // zero per-warp buffers so an invalid tail edge computes on finite data
        for (int i = tid; i < WARPS_PER_BLK * 3072; i += THREADS_BLK) bufs[i] = 0.f;
    }
    __syncthreads();

    const int warp = tid >> 5, lane = tid & 31;
    const int eidx = lane >> 4, l16 = lane & 15;    // half-warp edge slot
    float* buf  = bufs + warp * 3072;
    float* qox  = buf;            // 512
    float* kbuf = buf + 512;      // 1024
    float* vbuf = buf + 1536;     // 1024
    float* ffb  = buf + 2560;     // 512

    const int* ei = type ? e1 : e0;
    const int  E  = type ? E1 : E0;
    float* accbase = g_acc + (size_t)type * NA_N * 256ull;
    int*   cntbase = g_cnt + type * NA_N;

    for (int e = bidx * (WARPS_PER_BLK * 2) + warp * 2; e < E; e += PAIR_STRIDE) {
        const bool v1 = (e + 1 < E);
        const int s0 = __ldg(ei + e);
        const int d0 = __ldg(ei + E + e);
        const int s1 = v1 ? __ldg(ei + e + 1) : s0;
        const int d1 = v1 ? __ldg(ei + E + e + 1) : d0;
        const int de = eidx ? d1 : d0;
        const int se = eidx ? s1 : s0;
        const float* dq_base = g_dstqkv + ((size_t)type * NA_N + de) * 768;

        // Gather k,v (dst+src) for own edge: 16 LDG.128 + 16 STS.128 per lane (2 edges)
        {
            const float4* gdq = reinterpret_cast<const float4*>(dq_base);
            const float4* gsk = reinterpret_cast<const float4*>(g_srckv + ((size_t)type * NA_N + se) * 512);
            float4* kb4 = reinterpret_cast<float4*>(kbuf + eidx * 512);
            float4* vb4 = reinterpret_cast<float4*>(vbuf + eidx * 512);
#pragma unroll
            for (int j = 0; j < 4; j++) {
                kb4[l16 + 16 * j]      = __ldg(gdq + 64  + l16 + 16 * j);
                vb4[l16 + 16 * j]      = __ldg(gdq + 128 + l16 + 16 * j);
                kb4[64 + l16 + 16 * j] = __ldg(gsk + l16 + 16 * j);
                vb4[64 + l16 + 16 * j] = __ldg(gsk + 64 + l16 + 16 * j);
            }
        }

        // xi residual prefetch into registers: coalesced LDG.32
        float xr0[8], xr1[8];
#pragma unroll
        for (int t = 0; t < 8; t++) {
            const int dd = (t >= 4) ? d1 : d0;
            const float* xp = xA + (size_t)dd * 256 + (t & 3) * 64;
            xr0[t] = __ldg(xp + lane);
            xr1[t] = __ldg(xp + lane + 32);
        }
        __syncwarp();

        // attention: 32 lanes = 2 edges x 4 heads x 4 query tokens.
        // q read straight from global (precomputed); o written to qox for the Wo GEMM.
        {
            const int h = (lane >> 2) & 3, s = lane & 3;
            const float4* qp4 = reinterpret_cast<const float4*>(dq_base + s * 64 + h * 16);
            float4 qa = __ldg(qp4), qb = __ldg(qp4 + 1), qc = __ldg(qp4 + 2), qd = __ldg(qp4 + 3);
            float q[16] = {qa.x, qa.y, qa.z, qa.w, qb.x, qb.y, qb.z, qb.w,
                           qc.x, qc.y, qc.z, qc.w, qd.x, qd.y, qd.z, qd.w};
            const float* kpe = kbuf + eidx * 512 + h * 16;
            const float* vpe = vbuf + eidx * 512 + h * 16;
            float scr[8];
#pragma unroll
            for (int t = 0; t < 8; t++) {
                const float* kp = kpe + t * 64;
                float a = 0.f;
#pragma unroll
                for (int d = 0; d < 16; d++) a = fmaf(q[d], kp[d], a);
                scr[t] = a * 0.25f;  // 1/sqrt(16)
            }
            float m = scr[0];
#pragma unroll
            for (int t = 1; t < 8; t++) m = fmaxf(m, scr[t]);
            float ssum = 0.f;
#pragma unroll
            for (int t = 0; t < 8; t++) { scr[t] = __expf(scr[t] - m); ssum += scr[t]; }
            float inv = 1.f / ssum;
            float o[16];
#pragma unroll
            for (int d = 0; d < 16; d++) o[d] = 0.f;
#pragma unroll
            for (int t = 0; t < 8; t++) {
                const float* vp = vpe + t * 64;
                float p = scr[t] * inv;
#pragma unroll
                for (int d = 0; d < 16; d++) o[d] = fmaf(p, vp[d], o[d]);
            }
            float* op = qox + eidx * 256 + s * 64 + h * 16;
#pragma unroll
            for (int d = 0; d < 16; d++) op[d] = o[d];
        }
        __syncwarp();

        // attn proj (S=8, both edges) + residual(regs) + LN1; rewrites qox
        {
            float a0[8], a1[8];
            mm64_core<8>(qox, 64, sWo, 64, lane, a0, a1);
            __syncwarp();
            float b0 = sbo[lane], b1 = sbo[lane + 32];
#pragma unroll
            for (int t = 0; t < 8; t++) {
                float r0 = a0[t] + b0 + xr0[t];
                float r1 = a1[t] + b1 + xr1[t];
                float y0, y1;
                ln_pair(r0, r1, sg1, sbe1, lane, y0, y1);
                qox[t * 64 + lane]      = y0;
                qox[t * 64 + lane + 32] = y1;
            }
        }
        __syncwarp();

        // FF1 (relu): qox -> ffb (S=8)
        mm64_store<8, true>(qox, 64, sW1, 64, sbf1, ffb, 64, lane);
        __syncwarp();

        // FF2 + residual(qox) + LN2 -> atomic scatter (guard invalid tail edge)
        {
            float a0[8], a1[8];
            mm64_core<8>(ffb, 64, sW2, 64, lane, a0, a1);
            float b0 = sbf2[lane], b1 = sbf2[lane + 32];
#pragma unroll
            for (int t = 0; t < 8; t++) {
                if (t < 4 || v1) {
                    const int dd = (t >= 4) ? d1 : d0;
                    float* accp = accbase + (size_t)dd * 256 + (t & 3) * 64;
                    float r0 = a0[t] + b0 + qox[t * 64 + lane];
                    float r1 = a1[t] + b1 + qox[t * 64 + lane + 32];
                    float y0, y1;
                    ln_pair(r0, r1, sg2, sbe2, lane, y0, y1);
                    atomicAdd(accp + lane, y0);
                    atomicAdd(accp + lane + 32, y1);
                }
            }
            if (lane == 0) {
                atomicAdd(cntbase + d0, 1);
                if (v1) atomicAdd(cntbase + d1, 1);
            }
        }
        __syncwarp();
    }
}

// ---------------------------------------------------------------------------
// final: mean across edge types, Wout per token, sum over tokens, softmax(32)
// one warp per node, 4 nodes per block
// ---------------------------------------------------------------------------
__global__ void __launch_bounds__(128) out_kernel(const float* __restrict__ Wout,
                                                  const float* __restrict__ bout,
                                                  float* __restrict__ out) {
    __shared__ float sW[2048];   // [c][o]
    __shared__ float sb[32];
    __shared__ float comb[4][256];
    const int tid = threadIdx.x;
    for (int i = tid; i < 2048; i += 128) { int o = i >> 6, c = i & 63; sW[c * 32 + o] = Wout[i]; }
    if (tid < 32) sb[tid] = bout[tid];
    __syncthreads();

    const int warp = tid >> 5, lane = tid & 31;
    const int n = blockIdx.x * 4 + warp;
    if (n >= NA_N) return;

    const int c0 = g_cnt[n], c1 = g_cnt[NA_N + n];
    const float i0 = (c0 > 0) ? 0.5f / (float)c0 : 0.f;
    const float i1 = (c1 > 0) ? 0.5f / (float)c1 : 0.f;
    const float* a0 = g_acc + (size_t)n * 256;
    const float* a1 = g_acc + (size_t)NA_N * 256 + (size_t)n * 256;
    float* cb = comb[warp];
#pragma unroll
    for (int j = 0; j < 8; j++) {
        int i = lane + 32 * j;
        cb[i] = a0[i] * i0 + a1[i] * i1;
    }
    __syncwarp();

    float h = 0.f;
#pragma unroll 4
    for (int i = 0; i < 256; i++) {
        int c = i & 63;
        h = fmaf(cb[i], sW[c * 32 + lane], h);
    }
    h += 4.f * sb[lane];

    float m = warp_max(h);
    float ex = __expf(h - m);
    float s = warp_sum(ex);
    out[(size_t)n * 32 + lane] = ex / s;
}

// ---------------------------------------------------------------------------
extern "C" void kernel_launch(void* const* d_in, const int* in_sizes, int n_in,
                              void* d_out, int out_size) {
    const float* xA   = (const float*)d_in[0];
    const float* xB   = (const float*)d_in[1];
    const int*   e0   = (const int*)d_in[2];
    const int*   e1   = (const int*)d_in[3];
    const float* Wb   = (const float*)d_in[4];
    const float* bb   = (const float*)d_in[5];
    const float* Wqkv = (const float*)d_in[6];
    const float* bqkv = (const float*)d_in[7];
    const float* Wo   = (const float*)d_in[8];
    const float* bo   = (const float*)d_in[9];
    const float* g1   = (const float*)d_in[10];
    const float* be1  = (const float*)d_in[11];
    const float* W1   = (const float*)d_in[12];
    const float* bf1  = (const float*)d_in[13];
    const float* W2   = (const float*)d_in[14];
    const float* bf2  = (const float*)d_in[15];
    const float* g2   = (const float*)d_in[16];
    const float* be2  = (const float*)d_in[17];
    const float* Wout = (const float*)d_in[18];
    const float* bout = (const float*)d_in[19];

    const int E0 = in_sizes[2] / 2;
    const int E1 = in_sizes[3] / 2;

    const int dst_smem  = (12288 + 192 + WARPS_PER_BLK * 256) * 4;
    const int src_smem  = (4096 + 12288 + 64 + 192 + WARPS_PER_BLK * 256) * 4;
    const int edge_smem = (3 * 4096 + 7 * 64 + WARPS_PER_BLK * 3072) * 4;   // 173,824 B
    cudaFuncSetAttribute(dstpre_kernel, cudaFuncAttributeMaxDynamicSharedMemorySize, dst_smem);
    cudaFuncSetAttribute(srcpre_kernel, cudaFuncAttributeMaxDynamicSharedMemorySize, src_smem);
    cudaFuncSetAttribute(edge_kernel,   cudaFuncAttributeMaxDynamicSharedMemorySize, edge_smem);

    zero_kernel<<<2048, 256>>>();
    dstpre_kernel<<<2 * 148, THREADS_BLK, dst_smem>>>(xA, Wqkv, bqkv);
    srcpre_kernel<<<2 * 148, THREADS_BLK, src_smem>>>(xA, xB, Wb, bb, Wqkv, bqkv);
    edge_kernel<<<2 * EDGE_BLOCKS, THREADS_BLK, edge_smem>>>(
        xA, e0, E0, e1, E1,
        Wo, bo, g1, be1, W1, bf1, W2, bf2, g2, be2);
    out_kernel<<<(NA_N + 3) / 4, 128>>>(Wout, bout, (float*)d_out);
}

// round 8
// speedup vs baseline: 1.5961x; 1.0772x over previous
#include <cuda_runtime.h>
#include <math.h>
#include <stdint.h>

// Problem constants (fixed-shape problem)
#define NA_N   40000
#define NB_N   40000
#define EPS_LN 1e-5f

#define WARPS_PER_BLK 12
#define EDGE_BLOCKS   148          // per edge type
#define THREADS_BLK   (WARPS_PER_BLK * 32)
#define PAIR_STRIDE   (EDGE_BLOCKS * WARPS_PER_BLK * 2)
#define NODE_STRIDE   (148 * WARPS_PER_BLK)

// Scratch (static device arrays; no runtime alloc)
__device__ float g_acc[2ull * NA_N * 256ull];
__device__ int   g_cnt[2 * NA_N];
// Precomputed per-(type,node) projections:
//   g_dstqkv[t][n][0:256)=q, [256:512)=k, [512:768)=v   (from xA, Wqkv[t])
//   g_srckv [t][n][0:256)=k, [256:512)=v                (fused (Wk·Wb)x form)
__device__ float g_dstqkv[2ull * NA_N * 768ull];
__device__ float g_srckv [2ull * NA_N * 512ull];
// Fused src weights: [t][c][128] (k|v feature columns), biases [t][128]
__device__ float g_wfuse[2 * 64 * 128];
__device__ float g_bfuse[2 * 128];

// ---------------------------------------------------------------------------
// helpers
// ---------------------------------------------------------------------------
__device__ __forceinline__ float warp_sum(float v) {
#pragma unroll
    for (int o = 16; o; o >>= 1) v += __shfl_xor_sync(0xffffffffu, v, o);
    return v;
}
__device__ __forceinline__ float warp_max(float v) {
#pragma unroll
    for (int o = 16; o; o >>= 1) v = fmaxf(v, __shfl_xor_sync(0xffffffffu, v, o));
    return v;
}

// Single-matrix GEMM core: out[s][f] partials over 64-dim reduction.
// Weights [c][f] in smem, lane owns (lane, lane+32) -> two LDS.32, conflict-free.
// Input rows read as broadcast float4 LDS.
template <int S>
__device__ __forceinline__ void mm64_core(const float* __restrict__ in, int in_stride,
                                          const float* __restrict__ Wt, int wstride,
                                          int lane, float* a0, float* a1) {
#pragma unroll
    for (int s = 0; s < S; s++) { a0[s] = 0.f; a1[s] = 0.f; }
#pragma unroll
    for (int c4 = 0; c4 < 16; c4++) {
        float4 xv[S];
#pragma unroll
        for (int s = 0; s < S; s++)
            xv[s] = *reinterpret_cast<const float4*>(in + s * in_stride + (c4 << 2));
#pragma unroll
        for (int j = 0; j < 4; j++) {
            const float* wrow = Wt + ((c4 << 2) + j) * wstride;
            float w0 = wrow[lane];
            float w1 = wrow[lane + 32];
#pragma unroll
            for (int s = 0; s < S; s++) {
                float xx = (j == 0) ? xv[s].x : (j == 1) ? xv[s].y : (j == 2) ? xv[s].z : xv[s].w;
                a0[s] = fmaf(xx, w0, a0[s]);
                a1[s] = fmaf(xx, w1, a1[s]);
            }
        }
    }
}

template <int S, bool RELU>
__device__ __forceinline__ void mm64_store(const float* __restrict__ in, int in_stride,
                                           const float* __restrict__ Wt, int wstride,
                                           const float* __restrict__ bias,
                                           float* __restrict__ out, int out_stride, int lane) {
    float a0[S], a1[S];
    mm64_core<S>(in, in_stride, Wt, wstride, lane, a0, a1);
    float b0 = bias[lane], b1 = bias[lane + 32];
#pragma unroll
    for (int s = 0; s < S; s++) {
        float r0 = a0[s] + b0, r1 = a1[s] + b1;
        if (RELU) { r0 = fmaxf(r0, 0.f); r1 = fmaxf(r1, 0.f); }
        out[s * out_stride + lane]      = r0;
        out[s * out_stride + lane + 32] = r1;
    }
}

// Fused multi-matrix sweep over W ([c][WSTRIDE] layout): M weight streams.
template <int M, int WSTRIDE>
__device__ __forceinline__ void mmqkv_core(const float* __restrict__ in,
                                           const float* __restrict__ Wq, const int* woff,
                                           int lane, float (*a0)[4], float (*a1)[4]) {
#pragma unroll
    for (int m = 0; m < M; m++)
#pragma unroll
        for (int s = 0; s < 4; s++) { a0[m][s] = 0.f; a1[m][s] = 0.f; }
#pragma unroll
    for (int c4 = 0; c4 < 16; c4++) {
        float4 xv[4];
#pragma unroll
        for (int s = 0; s < 4; s++)
            xv[s] = *reinterpret_cast<const float4*>(in + s * 64 + (c4 << 2));
#pragma unroll
        for (int j = 0; j < 4; j++) {
            const float* wrow = Wq + ((c4 << 2) + j) * WSTRIDE;
            float w0[M], w1[M];
#pragma unroll
            for (int m = 0; m < M; m++) {
                w0[m] = wrow[woff[m] + lane];
                w1[m] = wrow[woff[m] + lane + 32];
            }
#pragma unroll
            for (int s = 0; s < 4; s++) {
                float xx = (j == 0) ? xv[s].x : (j == 1) ? xv[s].y : (j == 2) ? xv[s].z : xv[s].w;
#pragma unroll
                for (int m = 0; m < M; m++) {
                    a0[m][s] = fmaf(xx, w0[m], a0[m][s]);
                    a1[m][s] = fmaf(xx, w1[m], a1[m][s]);
                }
            }
        }
    }
}

// LayerNorm over 64 features distributed as (lane, lane+32).
__device__ __forceinline__ void ln_pair(float r0, float r1,
                                        const float* __restrict__ g, const float* __restrict__ b,
                                        int lane, float& y0, float& y1) {
    float m = warp_sum(r0 + r1) * (1.f / 64.f);
    float d0 = r0 - m, d1 = r1 - m;
    float v = warp_sum(d0 * d0 + d1 * d1) * (1.f / 64.f);
    float inv = rsqrtf(v + EPS_LN);
    y0 = d0 * inv * g[lane]      + b[lane];
    y1 = d1 * inv * g[lane + 32] + b[lane + 32];
}

// ---------------------------------------------------------------------------
// zero scratch
// ---------------------------------------------------------------------------
__global__ void zero_kernel() {
    size_t i = (size_t)blockIdx.x * blockDim.x + threadIdx.x;
    size_t stride = (size_t)gridDim.x * blockDim.x;
    float4* p = reinterpret_cast<float4*>(g_acc);
    size_t n4 = (2ull * NA_N * 256ull) / 4;
    for (size_t j = i; j < n4; j += stride) p[j] = make_float4(0.f, 0.f, 0.f, 0.f);
    for (size_t j = i; j < 2 * NA_N; j += stride) g_cnt[j] = 0;
}

// ---------------------------------------------------------------------------
// Fold b_proj into src k/v:  Wf[t][c][f] = sum_m Wqkv[t][64+f][m] * Wb[t][m][c]
//                            bf[t][f]   = bqkv[t][64+f] + sum_m Wqkv[t][64+f][m] * bb[t][m]
// ---------------------------------------------------------------------------
__global__ void fuse_kernel(const float* __restrict__ Wb, const float* __restrict__ bb,
                            const float* __restrict__ Wqkv, const float* __restrict__ bqkv) {
    const int t = blockIdx.x;
    const int tid = threadIdx.x;
    for (int idx = tid; idx < 64 * 128; idx += blockDim.x) {
        int c = idx >> 7, f = idx & 127;
        const float* wq = Wqkv + t * 12288 + (64 + f) * 64;
        const float* wb = Wb + t * 4096;
        float s = 0.f;
#pragma unroll 8
        for (int m = 0; m < 64; m++) s = fmaf(wq[m], wb[m * 64 + c], s);
        g_wfuse[t * 8192 + c * 128 + f] = s;
    }
    if (tid < 128) {
        const float* wq = Wqkv + t * 12288 + (64 + tid) * 64;
        const float* bbp = bb + t * 64;
        float s = bqkv[t * 192 + 64 + tid];
#pragma unroll 8
        for (int m = 0; m < 64; m++) s = fmaf(wq[m], bbp[m], s);
        g_bfuse[t * 128 + tid] = s;
    }
}

// ---------------------------------------------------------------------------
// Precompute per-(type, A-node): q,k,v of the dst tokens. One warp per node.
// ---------------------------------------------------------------------------
__global__ void __launch_bounds__(THREADS_BLK, 1) dstpre_kernel(
    const float* __restrict__ xA,
    const float* __restrict__ Wqkv, const float* __restrict__ bqkv) {
    extern __shared__ float smem[];
    float* sWq = smem;            // [c][192]
    float* sbq = sWq + 12288;     // 192
    float* bufs = sbq + 192;      // WARPS * 256

    const int type = blockIdx.x & 1;
    const int bidx = blockIdx.x >> 1;
    const int tid = threadIdx.x;
    {
        const float* p = Wqkv + type * 12288;
        for (int i = tid; i < 12288; i += THREADS_BLK) { int g = i >> 6, c = i & 63; sWq[c * 192 + g] = p[i]; }
        if (tid < 192) sbq[tid] = bqkv[type * 192 + tid];
    }
    __syncthreads();

    const int warp = tid >> 5, lane = tid & 31;
    float* buf = bufs + warp * 256;
    const int woff3[3] = {0, 64, 128};

    for (int n = bidx * WARPS_PER_BLK + warp; n < NA_N; n += NODE_STRIDE) {
        const float4* gx = reinterpret_cast<const float4*>(xA + (size_t)n * 256);
        reinterpret_cast<float4*>(buf)[lane]      = __ldg(gx + lane);
        reinterpret_cast<float4*>(buf)[lane + 32] = __ldg(gx + lane + 32);
        __syncwarp();
        float a0[3][4], a1[3][4];
        mmqkv_core<3, 192>(buf, sWq, woff3, lane, a0, a1);
        float* outp = g_dstqkv + ((size_t)type * NA_N + n) * 768;
#pragma unroll
        for (int m = 0; m < 3; m++) {
            float b0 = sbq[woff3[m] + lane], b1 = sbq[woff3[m] + lane + 32];
#pragma unroll
            for (int s = 0; s < 4; s++) {
                outp[m * 256 + s * 64 + lane]      = a0[m][s] + b0;
                outp[m * 256 + s * 64 + lane + 32] = a1[m][s] + b1;
            }
        }
        __syncwarp();
    }
}

// ---------------------------------------------------------------------------
// Precompute per-(type, src-node): k,v of projected src tokens, via fused weights.
// ---------------------------------------------------------------------------
__global__ void __launch_bounds__(THREADS_BLK, 1) srcpre_kernel(
    const float* __restrict__ xA, const float* __restrict__ xB) {
    extern __shared__ float smem[];
    float* sWf = smem;            // [c][128]
    float* sbf = sWf + 8192;      // 128
    float* bufs = sbf + 128;      // WARPS * 256

    const int type = blockIdx.x & 1;
    const int bidx = blockIdx.x >> 1;
    const int tid = threadIdx.x;
    {
        const float* p = g_wfuse + type * 8192;
        for (int i = tid; i < 8192; i += THREADS_BLK) sWf[i] = p[i];
        if (tid < 128) sbf[tid] = g_bfuse[type * 128 + tid];
    }
    __syncthreads();

    const int warp = tid >> 5, lane = tid & 31;
    float* buf = bufs + warp * 256;
    const float* xsrc = type ? xA : xB;
    const int NSRC = NA_N;   // both node sets are 40000
    const int woff2[2] = {0, 64};

    for (int n = bidx * WARPS_PER_BLK + warp; n < NSRC; n += NODE_STRIDE) {
        const float4* gx = reinterpret_cast<const float4*>(xsrc + (size_t)n * 256);
        reinterpret_cast<float4*>(buf)[lane]      = __ldg(gx + lane);
        reinterpret_cast<float4*>(buf)[lane + 32] = __ldg(gx + lane + 32);
        __syncwarp();
        float a0[2][4], a1[2][4];
        mmqkv_core<2, 128>(buf, sWf, woff2, lane, a0, a1);
        float* outp = g_srckv + ((size_t)type * NA_N + n) * 512;
#pragma unroll
        for (int m = 0; m < 2; m++) {
            float b0 = sbf[woff2[m] + lane], b1 = sbf[woff2[m] + lane + 32];
#pragma unroll
            for (int s = 0; s < 4; s++) {
                outp[m * 256 + s * 64 + lane]      = a0[m][s] + b0;
                outp[m * 256 + s * 64 + lane + 32] = a1[m][s] + b1;
            }
        }
        __syncwarp();
    }
}

// ---------------------------------------------------------------------------
// per-edge: TWO edges per warp. Gather precomputed k/v, attention (32 lanes =
// 2 edges x 4 heads x 4 tokens, q straight from global), Wo+LN1, FFN+LN2,
// scatter. Per-warp smem (2560 floats):
//   qox[512 = 2x256] | kbuf[1024] (ffb aliases this) | vbuf[1024]
// ---------------------------------------------------------------------------
__global__ void __launch_bounds__(THREADS_BLK, 1) edge_kernel(
    const float* __restrict__ xA,
    const int* __restrict__ e0, int E0,
    const int* __restrict__ e1, int E1,
    const float* __restrict__ Wo,  const float* __restrict__ bo,
    const float* __restrict__ g1,  const float* __restrict__ be1,
    const float* __restrict__ W1,  const float* __restrict__ bf1,
    const float* __restrict__ W2,  const float* __restrict__ bf2,
    const float* __restrict__ g2,  const float* __restrict__ be2) {
    extern __shared__ float smem[];
    float* sWo  = smem;              // [c][f]  64*64
    float* sW1  = sWo + 4096;        // [c][f]  64*64
    float* sW2  = sW1 + 4096;        // [f][c]  64*64
    float* sbo  = sW2 + 4096;        // 64
    float* sbf1 = sbo + 64;
    float* sbf2 = sbf1 + 64;
    float* sg1  = sbf2 + 64;
    float* sbe1 = sg1 + 64;
    float* sg2  = sbe1 + 64;
    float* sbe2 = sg2 + 64;
    float* bufs = sbe2 + 64;         // WARPS * 2560

    const int type = blockIdx.x & 1;
    const int bidx = blockIdx.x >> 1;
    const int tid = threadIdx.x;
    {
        const float* p = Wo + type * 4096;
        for (int i = tid; i < 4096; i += THREADS_BLK) { int f = i >> 6, c = i & 63; sWo[c * 64 + f] = p[i]; }
        p = W1 + type * 4096;
        for (int i = tid; i < 4096; i += THREADS_BLK) { int f = i >> 6, c = i & 63; sW1[c * 64 + f] = p[i]; }
        p = W2 + type * 4096;
        for (int i = tid; i < 4096; i += THREADS_BLK) { int c = i >> 6, f = i & 63; sW2[f * 64 + c] = p[i]; }
        if (tid < 64) sbo[tid]  = bo[type * 64 + tid];
        if (tid < 64) sbf1[tid] = bf1[type * 64 + tid];
        if (tid < 64) sbf2[tid] = bf2[type * 64 + tid];
        if (tid < 64) sg1[tid]  = g1[type * 64 + tid];
        if (tid < 64) sbe1[tid] = be1[type * 64 + tid];
        if (tid < 64) sg2[tid]  = g2[type * 64 + tid];
        if (tid < 64) sbe2[tid] = be2[type * 64 + tid];
        // zero per-warp buffers so an invalid tail edge computes on finite data
        for (int i = tid; i < WARPS_PER_BLK * 2560; i += THREADS_BLK) bufs[i] = 0.f;
    }
    __syncthreads();

    const int warp = tid >> 5, lane = tid & 31;
    const int eidx = lane >> 4, l16 = lane & 15;    // half-warp edge slot
    float* buf  = bufs + warp * 2560;
    float* qox  = buf;            // 512
    float* kbuf = buf + 512;      // 1024 (k dead after attention -> ffb aliases)
    float* vbuf = buf + 1536;     // 1024
    float* ffb  = kbuf;           // 512 used

    const int* ei = type ? e1 : e0;
    const int  E  = type ? E1 : E0;
    float* accbase = g_acc + (size_t)type * NA_N * 256ull;
    int*   cntbase = g_cnt + type * NA_N;

    for (int e = bidx * (WARPS_PER_BLK * 2) + warp * 2; e < E; e += PAIR_STRIDE) {
        const bool v1 = (e + 1 < E);
        const int s0 = __ldg(ei + e);
        const int d0 = __ldg(ei + E + e);
        const int s1 = v1 ? __ldg(ei + e + 1) : s0;
        const int d1 = v1 ? __ldg(ei + E + e + 1) : d0;
        const int de = eidx ? d1 : d0;
        const int se = eidx ? s1 : s0;
        const float* dq_base = g_dstqkv + ((size_t)type * NA_N + de) * 768;

        // Gather k,v (dst+src) for own edge: 16 LDG.128 + 16 STS.128 per lane (2 edges)
        {
            const float4* gdq = reinterpret_cast<const float4*>(dq_base);
            const float4* gsk = reinterpret_cast<const float4*>(g_srckv + ((size_t)type * NA_N + se) * 512);
            float4* kb4 = reinterpret_cast<float4*>(kbuf + eidx * 512);
            float4* vb4 = reinterpret_cast<float4*>(vbuf + eidx * 512);
#pragma unroll
            for (int j = 0; j < 4; j++) {
                kb4[l16 + 16 * j]      = __ldg(gdq + 64  + l16 + 16 * j);
                vb4[l16 + 16 * j]      = __ldg(gdq + 128 + l16 + 16 * j);
                kb4[64 + l16 + 16 * j] = __ldg(gsk + l16 + 16 * j);
                vb4[64 + l16 + 16 * j] = __ldg(gsk + 64 + l16 + 16 * j);
            }
        }

        // xi residual prefetch into registers: coalesced LDG.32
        float xr0[8], xr1[8];
#pragma unroll
        for (int t = 0; t < 8; t++) {
            const int dd = (t >= 4) ? d1 : d0;
            const float* xp = xA + (size_t)dd * 256 + (t & 3) * 64;
            xr0[t] = __ldg(xp + lane);
            xr1[t] = __ldg(xp + lane + 32);
        }
        __syncwarp();

        // attention: 32 lanes = 2 edges x 4 heads x 4 query tokens.
        // q read straight from global (precomputed); o written to qox for the Wo GEMM.
        {
            const int h = (lane >> 2) & 3, s = lane & 3;
            const float4* qp4 = reinterpret_cast<const float4*>(dq_base + s * 64 + h * 16);
            float4 qa = __ldg(qp4), qb = __ldg(qp4 + 1), qc = __ldg(qp4 + 2), qd = __ldg(qp4 + 3);
            float q[16] = {qa.x, qa.y, qa.z, qa.w, qb.x, qb.y, qb.z, qb.w,
                           qc.x, qc.y, qc.z, qc.w, qd.x, qd.y, qd.z, qd.w};
            const float* kpe = kbuf + eidx * 512 + h * 16;
            const float* vpe = vbuf + eidx * 512 + h * 16;
            float scr[8];
#pragma unroll
            for (int t = 0; t < 8; t++) {
                const float* kp = kpe + t * 64;
                float a = 0.f;
#pragma unroll
                for (int d = 0; d < 16; d++) a = fmaf(q[d], kp[d], a);
                scr[t] = a * 0.25f;  // 1/sqrt(16)
            }
            float m = scr[0];
#pragma unroll
            for (int t = 1; t < 8; t++) m = fmaxf(m, scr[t]);
            float ssum = 0.f;
#pragma unroll
            for (int t = 0; t < 8; t++) { scr[t] = __expf(scr[t] - m); ssum += scr[t]; }
            float inv = 1.f / ssum;
            float o[16];
#pragma unroll
            for (int d = 0; d < 16; d++) o[d] = 0.f;
#pragma unroll
            for (int t = 0; t < 8; t++) {
                const float* vp = vpe + t * 64;
                float p = scr[t] * inv;
#pragma unroll
                for (int d = 0; d < 16; d++) o[d] = fmaf(p, vp[d], o[d]);
            }
            float* op = qox + eidx * 256 + s * 64 + h * 16;
#pragma unroll
            for (int d = 0; d < 16; d++) op[d] = o[d];
        }
        __syncwarp();

        // attn proj (S=8, both edges) + residual(regs) + LN1; rewrites qox
        {
            float a0[8], a1[8];
            mm64_core<8>(qox, 64, sWo, 64, lane, a0, a1);
            __syncwarp();
            float b0 = sbo[lane], b1 = sbo[lane + 32];
#pragma unroll
            for (int t = 0; t < 8; t++) {
                float r0 = a0[t] + b0 + xr0[t];
                float r1 = a1[t] + b1 + xr1[t];
                float y0, y1;
                ln_pair(r0, r1, sg1, sbe1, lane, y0, y1);
                qox[t * 64 + lane]      = y0;
                qox[t * 64 + lane + 32] = y1;
            }
        }
        __syncwarp();

        // FF1 (relu): qox -> ffb (aliases kbuf; k is dead)
        mm64_store<8, true>(qox, 64, sW1, 64, sbf1, ffb, 64, lane);
        __syncwarp();

        // FF2 + residual(qox) + LN2 -> atomic scatter (guard invalid tail edge)
        {
            float a0[8], a1[8];
            mm64_core<8>(ffb, 64, sW2, 64, lane, a0, a1);
            float b0 = sbf2[lane], b1 = sbf2[lane + 32];
#pragma unroll
            for (int t = 0; t < 8; t++) {
                if (t < 4 || v1) {
                    const int dd = (t >= 4) ? d1 : d0;
                    float* accp = accbase + (size_t)dd * 256 + (t & 3) * 64;
                    float r0 = a0[t] + b0 + qox[t * 64 + lane];
                    float r1 = a1[t] + b1 + qox[t * 64 + lane + 32];
                    float y0, y1;
                    ln_pair(r0, r1, sg2, sbe2, lane, y0, y1);
                    atomicAdd(accp + lane, y0);
                    atomicAdd(accp + lane + 32, y1);
                }
            }
            if (lane == 0) {
                atomicAdd(cntbase + d0, 1);
                if (v1) atomicAdd(cntbase + d1, 1);
            }
        }
        __syncwarp();
    }
}

// ---------------------------------------------------------------------------
// final: mean across edge types, Wout per token, sum over tokens, softmax(32)
// one warp per node, 4 nodes per block
// ---------------------------------------------------------------------------
__global__ void __launch_bounds__(128) out_kernel(const float* __restrict__ Wout,
                                                  const float* __restrict__ bout,
                                                  float* __restrict__ out) {
    __shared__ float sW[2048];   // [c][o]
    __shared__ float sb[32];
    __shared__ float comb[4][256];
    const int tid = threadIdx.x;
    for (int i = tid; i < 2048; i += 128) { int o = i >> 6, c = i & 63; sW[c * 32 + o] = Wout[i]; }
    if (tid < 32) sb[tid] = bout[tid];
    __syncthreads();

    const int warp = tid >> 5, lane = tid & 31;
    const int n = blockIdx.x * 4 + warp;
    if (n >= NA_N) return;

    const int c0 = g_cnt[n], c1 = g_cnt[NA_N + n];
    const float i0 = (c0 > 0) ? 0.5f / (float)c0 : 0.f;
    const float i1 = (c1 > 0) ? 0.5f / (float)c1 : 0.f;
    const float* a0 = g_acc + (size_t)n * 256;
    const float* a1 = g_acc + (size_t)NA_N * 256 + (size_t)n * 256;
    float* cb = comb[warp];
#pragma unroll
    for (int j = 0; j < 8; j++) {
        int i = lane + 32 * j;
        cb[i] = a0[i] * i0 + a1[i] * i1;
    }
    __syncwarp();

    float h = 0.f;
#pragma unroll 4
    for (int i = 0; i < 256; i++) {
        int c = i & 63;
        h = fmaf(cb[i], sW[c * 32 + lane], h);
    }
    h += 4.f * sb[lane];

    float m = warp_max(h);
    float ex = __expf(h - m);
    float s = warp_sum(ex);
    out[(size_t)n * 32 + lane] = ex / s;
}

// ---------------------------------------------------------------------------
extern "C" void kernel_launch(void* const* d_in, const int* in_sizes, int n_in,
                              void* d_out, int out_size) {
    const float* xA   = (const float*)d_in[0];
    const float* xB   = (const float*)d_in[1];
    const int*   e0   = (const int*)d_in[2];
    const int*   e1   = (const int*)d_in[3];
    const float* Wb   = (const float*)d_in[4];
    const float* bb   = (const float*)d_in[5];
    const float* Wqkv = (const float*)d_in[6];
    const float* bqkv = (const float*)d_in[7];
    const float* Wo   = (const float*)d_in[8];
    const float* bo   = (const float*)d_in[9];
    const float* g1   = (const float*)d_in[10];
    const float* be1  = (const float*)d_in[11];
    const float* W1   = (const float*)d_in[12];
    const float* bf1  = (const float*)d_in[13];
    const float* W2   = (const float*)d_in[14];
    const float* bf2  = (const float*)d_in[15];
    const float* g2   = (const float*)d_in[16];
    const float* be2  = (const float*)d_in[17];
    const float* Wout = (const float*)d_in[18];
    const float* bout = (const float*)d_in[19];

    const int E0 = in_sizes[2] / 2;
    const int E1 = in_sizes[3] / 2;

    const int dst_smem  = (12288 + 192 + WARPS_PER_BLK * 256) * 4;                 // 62,208 B
    const int src_smem  = (8192 + 128 + WARPS_PER_BLK * 256) * 4;                  // 45,568 B
    const int edge_smem = (3 * 4096 + 7 * 64 + WARPS_PER_BLK * 2560) * 4;          // 173,824 B
    cudaFuncSetAttribute(dstpre_kernel, cudaFuncAttributeMaxDynamicSharedMemorySize, dst_smem);
    cudaFuncSetAttribute(srcpre_kernel, cudaFuncAttributeMaxDynamicSharedMemorySize, src_smem);
    cudaFuncSetAttribute(edge_kernel,   cudaFuncAttributeMaxDynamicSharedMemorySize, edge_smem);

    zero_kernel<<<2048, 256>>>();
    fuse_kernel<<<2, 256>>>(Wb, bb, Wqkv, bqkv);
    dstpre_kernel<<<2 * 148, THREADS_BLK, dst_smem>>>(xA, Wqkv, bqkv);
    srcpre_kernel<<<2 * 148, THREADS_BLK, src_smem>>>(xA, xB);
    edge_kernel<<<2 * EDGE_BLOCKS, THREADS_BLK, edge_smem>>>(
        xA, e0, E0, e1, E1,
        Wo, bo, g1, be1, W1, bf1, W2, bf2, g2, be2);
    out_kernel<<<(NA_N + 3) / 4, 128>>>(Wout, bout, (float*)d_out);
}